// round 6
// baseline (speedup 1.0000x reference)
#include <cuda_runtime.h>
#include <cuda_bf16.h>
#include <math.h>
#include <stdint.h>

#define BATCH 128
#define NOSC  1024
#define STEPS 10
#define DT    0.1f
#define BN    (BATCH*NOSC)

#define TM 32
#define TN 32
#define KS 64
#define NSTAGE (NOSC/KS)      // 16
#define LDA 72                // smem row stride (bf16): 144B, ldmatrix conflict-free
#define TILE_E (32*LDA)
#define STG_E  (3*TILE_E)
#define SMEM_BYTES (4*STG_E*2)  // 4-stage ring = 55296 B
#define FPAD 8                // 32B padding per flag

// ---------------- persistent device state (no allocation allowed) -------------
__device__ float          g_theta[BN];
__device__ __nv_bfloat16  g_sinb[3][BN];   // 3-way rotation (WAR-safe, see proof)
__device__ __nv_bfloat16  g_cosb[3][BN];
__device__ __nv_bfloat16  g_Kb[NOSC*NOSC];
__device__ int            g_flag[4*32*FPAD];   // [m_tile][n_tile] progress

// ---------------- helpers -----------------------------------------------------
__device__ __forceinline__ uint32_t s2u(const void* p) {
    return (uint32_t)__cvta_generic_to_shared(p);
}
__device__ __forceinline__ void cp16cg(void* dst, const void* src) {  // L1-bypass
    asm volatile("cp.async.cg.shared.global [%0], [%1], 16;"
                 :: "r"(s2u(dst)), "l"(src) : "memory");
}
__device__ __forceinline__ void cp16ca(void* dst, const void* src) {  // L1-cached
    asm volatile("cp.async.ca.shared.global [%0], [%1], 16;"
                 :: "r"(s2u(dst)), "l"(src) : "memory");
}
__device__ __forceinline__ void ldsm4(uint32_t& r0, uint32_t& r1, uint32_t& r2,
                                      uint32_t& r3, const void* p) {
    asm volatile("ldmatrix.sync.aligned.m8n8.x4.shared.b16 {%0,%1,%2,%3}, [%4];"
                 : "=r"(r0), "=r"(r1), "=r"(r2), "=r"(r3) : "r"(s2u(p)));
}
__device__ __forceinline__ void ldsm2(uint32_t& r0, uint32_t& r1, const void* p) {
    asm volatile("ldmatrix.sync.aligned.m8n8.x2.shared.b16 {%0,%1}, [%2];"
                 : "=r"(r0), "=r"(r1) : "r"(s2u(p)));
}
__device__ __forceinline__ void mma16816(float* d, const uint32_t* a,
                                         uint32_t b0, uint32_t b1) {
    asm volatile(
        "mma.sync.aligned.m16n8k16.row.col.f32.bf16.bf16.f32 "
        "{%0,%1,%2,%3}, {%4,%5,%6,%7}, {%8,%9}, {%0,%1,%2,%3};"
        : "+f"(d[0]), "+f"(d[1]), "+f"(d[2]), "+f"(d[3])
        : "r"(a[0]), "r"(a[1]), "r"(a[2]), "r"(a[3]), "r"(b0), "r"(b1));
}

// ---------------- init: theta/sin/cos(buf 0) + K -> bf16 + flags reset --------
__global__ void init_kernel(const float* __restrict__ theta_init,
                            const float* __restrict__ K) {
    int idx = blockIdx.x * blockDim.x + threadIdx.x;
    if (idx < 4 * 32 * FPAD) g_flag[idx] = 0;
    g_Kb[idx] = __float2bfloat16(K[idx]);
    if (idx < BN) {
        float t = theta_init[idx];
        g_theta[idx]   = t;
        g_sinb[0][idx] = __float2bfloat16(sinf(t));
        g_cosb[0][idx] = __float2bfloat16(cosf(t));
    }
}

// ---------------- persistent dataflow-pipelined simulation --------------------
__global__ __launch_bounds__(256, 1) void sim_kernel(const float* __restrict__ omega,
                                                     const float* __restrict__ kg) {
    extern __shared__ __nv_bfloat16 sm[];

    const int tid  = threadIdx.x;
    const int lane = tid & 31;
    const int wid  = tid >> 5;
    const int ntb  = blockIdx.x;          // n-tile 0..31
    const int mtb  = blockIdx.y;          // m-tile 0..3
    const int n0   = ntb * TN;
    const int m0   = mtb * TM;
    const int wy   = wid & 1;
    const int wn   = wid >> 1;

    const int lr = tid >> 3;
    const int lc = (tid & 7) * 8;

    const int ar  = wy * 16 + ((lane >> 3) & 1) * 8 + (lane & 7);
    const int l15 = lane & 15;
    const int br  = wn * 8 + (l15 & 7);
    const int bkh = ((l15 >> 3) & 1) * 8;

    // owned epilogue coords
    const int g   = lane >> 2, tig = lane & 3;
    const int oscb = n0 + wn * 8 + tig * 2;
    const float scale = kg[0] * (1.0f / NOSC);
    const float om0 = omega[oscb], om1 = omega[oscb + 1];

    volatile int* flg = g_flag + mtb * 32 * FPAD;
    const int myflag = mtb * 32 * FPAD + ntb * FPAD;

    float th[2][2], so[2][2], co[2][2];
#pragma unroll
    for (int half = 0; half < 2; half++) {
        int m = m0 + wy * 16 + half * 8 + g;
#pragma unroll
        for (int cc = 0; cc < 2; cc++) {
            float t = g_theta[m * NOSC + oscb + cc];
            th[half][cc] = t;
            so[half][cc] = sinf(t);
            co[half][cc] = cosf(t);
        }
    }

#pragma unroll 1
    for (int s = 0; s < STEPS; s++) {
        const __nv_bfloat16* sin_r = g_sinb[s % 3];
        const __nv_bfloat16* cos_r = g_cosb[s % 3];
        const int wb = (s + 1) % 3;

        auto poll = [&](int st_i) {      // wait for the 2 writer tiles of chunk st_i
            if (s > 0) {
                while (flg[(2 * st_i)     * FPAD] < s) { }
                while (flg[(2 * st_i + 1) * FPAD] < s) { }
            }
        };
        auto load_stage = [&](int st_i) {
            __nv_bfloat16* st = sm + (st_i & 3) * STG_E;
            const int k0 = st_i * KS;
            cp16cg(st + lr * LDA + lc,              sin_r + (size_t)(m0 + lr) * NOSC + k0 + lc);
            cp16cg(st + TILE_E + lr * LDA + lc,     cos_r + (size_t)(m0 + lr) * NOSC + k0 + lc);
            cp16ca(st + 2 * TILE_E + lr * LDA + lc, g_Kb  + (size_t)(n0 + lr) * NOSC + k0 + lc);
            asm volatile("cp.async.commit_group;" ::: "memory");
        };

        float aS[4] = {}, aC[4] = {};
        poll(0); load_stage(0);
        poll(1); load_stage(1);

#pragma unroll 1
        for (int st_i = 0; st_i < NSTAGE; st_i++) {
            if (st_i + 2 < NSTAGE) {
                poll(st_i + 2);
                load_stage(st_i + 2);
                asm volatile("cp.async.wait_group 2;" ::: "memory");
            } else if (st_i + 1 < NSTAGE) {
                asm volatile("cp.async.wait_group 1;" ::: "memory");
            } else {
                asm volatile("cp.async.wait_group 0;" ::: "memory");
            }
            __syncthreads();

            const __nv_bfloat16* st = sm + (st_i & 3) * STG_E;
#pragma unroll
            for (int kk = 0; kk < 4; kk++) {
                const int k0 = kk * 16;
                const int ac = k0 + (lane >> 4) * 8;
                uint32_t sa[4], ca[4], b0, b1;
                ldsm4(sa[0], sa[1], sa[2], sa[3], st + ar * LDA + ac);
                ldsm4(ca[0], ca[1], ca[2], ca[3], st + TILE_E + ar * LDA + ac);
                ldsm2(b0, b1, st + 2 * TILE_E + br * LDA + k0 + bkh);
                mma16816(aS, sa, b0, b1);
                mma16816(aC, ca, b0, b1);
            }
        }

        // ---- epilogue: register-resident phase update ------------------------
#pragma unroll
        for (int half = 0; half < 2; half++) {
#pragma unroll
            for (int cc = 0; cc < 2; cc++) {
                float S = aS[half * 2 + cc], C = aC[half * 2 + cc];
                float om = cc ? om1 : om0;
                float t2 = th[half][cc]
                         + DT * (om + scale * (co[half][cc] * S - so[half][cc] * C));
                float sn, cn;
                __sincosf(t2, &sn, &cn);
                th[half][cc] = t2;          // unwrapped; wrap is 2*pi-invariant
                so[half][cc] = sn;
                co[half][cc] = cn;
            }
        }

        if (s < STEPS - 1) {
            // publish bf16 sin/cos, then release the tile flag
#pragma unroll
            for (int half = 0; half < 2; half++) {
                int m = m0 + wy * 16 + half * 8 + g;
                *(__nv_bfloat162*)&g_sinb[wb][m * NOSC + oscb] =
                    __floats2bfloat162_rn(so[half][0 + 2 * 0], 0.f),  // placeholder overwritten below
                *(__nv_bfloat162*)&g_sinb[wb][m * NOSC + oscb] =
                    __floats2bfloat162_rn(so[half][0], so[half][1]);
                *(__nv_bfloat162*)&g_cosb[wb][m * NOSC + oscb] =
                    __floats2bfloat162_rn(co[half][0], co[half][1]);
            }
            __threadfence();
            __syncthreads();                 // all stores fenced before flag bump
            if (tid == 0) ((volatile int*)g_flag)[myflag] = s + 1;
        }
    }

    // ---- write final theta ----------------------------------------------------
#pragma unroll
    for (int half = 0; half < 2; half++) {
        int m = m0 + wy * 16 + half * 8 + g;
#pragma unroll
        for (int cc = 0; cc < 2; cc++)
            g_theta[m * NOSC + oscb + cc] = th[half][cc];
    }
}

// ---------------- finalize: wrap + coherence (accurate fp32) ------------------
__global__ void finalize_kernel(float* __restrict__ out) {
    __shared__ float rs[256], rc[256];
    const int b = blockIdx.x, tid = threadIdx.x;
    float ss = 0.f, cs = 0.f;
    for (int j = tid; j < NOSC; j += 256) {
        int idx = b * NOSC + j;
        float t = g_theta[idx];
        float sn = sinf(t), cn = cosf(t);
        out[idx] = atan2f(sn, cn);        // wrap to (-pi, pi], matches reference
        ss += sn; cs += cn;
    }
    rs[tid] = ss; rc[tid] = cs;
    __syncthreads();
    for (int off = 128; off > 0; off >>= 1) {
        if (tid < off) { rs[tid] += rs[tid + off]; rc[tid] += rc[tid + off]; }
        __syncthreads();
    }
    if (tid == 0) {
        float sm2 = rs[0] * (1.0f / NOSC);
        float cm  = rc[0] * (1.0f / NOSC);
        out[BN + b] = sqrtf(cm * cm + sm2 * sm2);
    }
}

extern "C" void kernel_launch(void* const* d_in, const int* in_sizes, int n_in,
                              void* d_out, int out_size) {
    const float* theta_init = (const float*)d_in[0];
    const float* K          = (const float*)d_in[1];
    const float* omega      = (const float*)d_in[2];
    const float* kglobal    = (const float*)d_in[3];
    float* out = (float*)d_out;

    cudaFuncSetAttribute(sim_kernel, cudaFuncAttributeMaxDynamicSharedMemorySize,
                         SMEM_BYTES);

    init_kernel<<<(NOSC * NOSC) / 256, 256>>>(theta_init, K);
    dim3 grid(NOSC / TN, BATCH / TM);     // (32, 4) = 128 CTAs, all co-resident
    sim_kernel<<<grid, 256, SMEM_BYTES>>>(omega, kglobal);
    finalize_kernel<<<BATCH, 256>>>(out);
}

// round 7
// speedup vs baseline: 1.8981x; 1.8981x over previous
#include <cuda_runtime.h>
#include <cuda_bf16.h>
#include <math.h>
#include <stdint.h>

#define BATCH 128
#define NOSC  1024
#define STEPS 10
#define DT    0.1f
#define BN    (BATCH*NOSC)

#define TM 32
#define TN 32
#define NCHUNK 16             // k-chunks of 64
#define TILE_B 4096           // 32 rows x 128B (64 bf16), swizzled, no padding
#define CHUNK_B (3*TILE_B)    // sin | cos | K per chunk
#define SMEM_BYTES (NCHUNK*CHUNK_B)   // 196608 B

// ---------------- persistent device state (no allocation allowed) -------------
__device__ float          g_theta[BN];
__device__ __nv_bfloat16  g_sinb[2][BN];   // double-buffered across steps
__device__ __nv_bfloat16  g_cosb[2][BN];
__device__ __nv_bfloat16  g_Kb[NOSC*NOSC];

// ---------------- helpers -----------------------------------------------------
__device__ __forceinline__ uint32_t s2u(const void* p) {
    return (uint32_t)__cvta_generic_to_shared(p);
}
__device__ __forceinline__ void cp16(uint32_t dst, const void* src) {
    asm volatile("cp.async.cg.shared.global [%0], [%1], 16;"
                 :: "r"(dst), "l"(src) : "memory");
}
__device__ __forceinline__ void ldsm4(uint32_t& r0, uint32_t& r1, uint32_t& r2,
                                      uint32_t& r3, uint32_t a) {
    asm volatile("ldmatrix.sync.aligned.m8n8.x4.shared.b16 {%0,%1,%2,%3}, [%4];"
                 : "=r"(r0), "=r"(r1), "=r"(r2), "=r"(r3) : "r"(a));
}
__device__ __forceinline__ void ldsm2(uint32_t& r0, uint32_t& r1, uint32_t a) {
    asm volatile("ldmatrix.sync.aligned.m8n8.x2.shared.b16 {%0,%1}, [%2];"
                 : "=r"(r0), "=r"(r1) : "r"(a));
}
__device__ __forceinline__ void mma16816(float* d, const uint32_t* a,
                                         uint32_t b0, uint32_t b1) {
    asm volatile(
        "mma.sync.aligned.m16n8k16.row.col.f32.bf16.bf16.f32 "
        "{%0,%1,%2,%3}, {%4,%5,%6,%7}, {%8,%9}, {%0,%1,%2,%3};"
        : "+f"(d[0]), "+f"(d[1]), "+f"(d[2]), "+f"(d[3])
        : "r"(a[0]), "r"(a[1]), "r"(a[2]), "r"(a[3]), "r"(b0), "r"(b1));
}

// ---------------- init (vectorized): theta/sin/cos(buf 0) + K -> bf16 ---------
__global__ void init_kernel(const float* __restrict__ theta_init,
                            const float* __restrict__ K) {
    int i4 = (blockIdx.x * blockDim.x + threadIdx.x) * 4;
    float4 k4 = *reinterpret_cast<const float4*>(&K[i4]);
    *reinterpret_cast<__nv_bfloat162*>(&g_Kb[i4]) =
        __floats2bfloat162_rn(k4.x, k4.y);
    *reinterpret_cast<__nv_bfloat162*>(&g_Kb[i4 + 2]) =
        __floats2bfloat162_rn(k4.z, k4.w);
    if (i4 < BN) {
        float4 t4 = *reinterpret_cast<const float4*>(&theta_init[i4]);
        *reinterpret_cast<float4*>(&g_theta[i4]) = t4;
        float s0 = sinf(t4.x), s1 = sinf(t4.y), s2 = sinf(t4.z), s3 = sinf(t4.w);
        float c0 = cosf(t4.x), c1 = cosf(t4.y), c2 = cosf(t4.z), c3 = cosf(t4.w);
        *reinterpret_cast<__nv_bfloat162*>(&g_sinb[0][i4])     = __floats2bfloat162_rn(s0, s1);
        *reinterpret_cast<__nv_bfloat162*>(&g_sinb[0][i4 + 2]) = __floats2bfloat162_rn(s2, s3);
        *reinterpret_cast<__nv_bfloat162*>(&g_cosb[0][i4])     = __floats2bfloat162_rn(c0, c1);
        *reinterpret_cast<__nv_bfloat162*>(&g_cosb[0][i4 + 2]) = __floats2bfloat162_rn(c2, c3);
    }
}

// ---------------- per-chunk compute (runtime chunk base, inlined) -------------
__device__ __forceinline__ void compute_chunk(
    uint32_t cb, uint32_t a_row, int ax, int asg,
    uint32_t b_row, int bx, int bsg, float* aS, float* aC)
{
#pragma unroll
    for (int kk = 0; kk < 4; kk++) {
        uint32_t aA = cb + a_row + (uint32_t)((((kk * 2 + asg) ^ ax)) << 4);
        uint32_t aB = cb + 2 * TILE_B + b_row + (uint32_t)((((kk * 2 + bsg) ^ bx)) << 4);
        uint32_t sa[4], ca[4], b0, b1;
        ldsm4(sa[0], sa[1], sa[2], sa[3], aA);
        ldsm4(ca[0], ca[1], ca[2], ca[3], aA + TILE_B);
        ldsm2(b0, b1, aB);
        mma16816(aS, sa, b0, b1);
        mma16816(aC, ca, b0, b1);
    }
}

// ---------------- fused step: whole-panel SMEM + 2 bf16 GEMMs + update --------
__global__ __launch_bounds__(256, 1) void step_kernel(const float* __restrict__ omega,
                                                      const float* __restrict__ kg,
                                                      int rb) {
    extern __shared__ __nv_bfloat16 sm[];
    const uint32_t sb = s2u(sm);

    const int tid  = threadIdx.x;
    const int lane = tid & 31;
    const int wid  = tid >> 5;
    const int n0   = blockIdx.x * TN;     // 32 n-tiles
    const int m0   = blockIdx.y * TM;     // 4 m-tiles
    const int wy   = wid & 1;
    const int wn   = wid >> 1;
    const int wbuf = rb ^ 1;

    const __nv_bfloat16* sin_r = g_sinb[rb];
    const __nv_bfloat16* cos_r = g_cosb[rb];

    // ---- issue the ENTIRE 192KB panel load up front (16 commit groups) -------
    {
        const int row = tid >> 3;                  // 0..31
        const int seg = tid & 7;                   // 16B segment in 128B row
        const uint32_t doff = (uint32_t)(row * 128 + ((seg ^ (row & 7)) << 4));
        const __nv_bfloat16* pS = sin_r + (size_t)(m0 + row) * NOSC + seg * 8;
        const __nv_bfloat16* pC = cos_r + (size_t)(m0 + row) * NOSC + seg * 8;
        const __nv_bfloat16* pB = g_Kb  + (size_t)(n0 + row) * NOSC + seg * 8;
#pragma unroll
        for (int c = 0; c < NCHUNK; c++) {
            cp16(sb + c * CHUNK_B + doff,              pS + c * 64);
            cp16(sb + c * CHUNK_B + TILE_B + doff,     pC + c * 64);
            cp16(sb + c * CHUNK_B + 2 * TILE_B + doff, pB + c * 64);
            asm volatile("cp.async.commit_group;" ::: "memory");
        }
    }

    // ---- fragment addressing (swizzled) --------------------------------------
    const int ar  = wy * 16 + ((lane >> 3) & 1) * 8 + (lane & 7);
    const int asg = lane >> 4;
    const uint32_t a_row = (uint32_t)(ar * 128);
    const int ax  = ar & 7;
    const int l15 = lane & 15;
    const int br  = wn * 8 + (l15 & 7);
    const int bsg = (l15 >> 3) & 1;
    const uint32_t b_row = (uint32_t)(br * 128);
    const int bx  = br & 7;

    float aS[4] = {}, aC[4] = {};

#define DO_CHUNK(c)                                                          \
    asm volatile("cp.async.wait_group %0;" :: "n"(NCHUNK - 1 - (c)) : "memory"); \
    __syncthreads();                                                         \
    compute_chunk(sb + (c) * CHUNK_B, a_row, ax, asg, b_row, bx, bsg, aS, aC);

    DO_CHUNK(0)  DO_CHUNK(1)  DO_CHUNK(2)  DO_CHUNK(3)
    DO_CHUNK(4)  DO_CHUNK(5)  DO_CHUNK(6)  DO_CHUNK(7)
    DO_CHUNK(8)  DO_CHUNK(9)  DO_CHUNK(10) DO_CHUNK(11)
    DO_CHUNK(12) DO_CHUNK(13) DO_CHUNK(14) DO_CHUNK(15)
#undef DO_CHUNK

    // ---- fused epilogue: Kuramoto phase update, wrap deferred to finalize ----
    const float scale = kg[0] * (1.0f / NOSC);
    const int g = lane >> 2, tig = lane & 3;
#pragma unroll
    for (int half = 0; half < 2; half++) {
        int m = m0 + wy * 16 + half * 8 + g;
#pragma unroll
        for (int cc = 0; cc < 2; cc++) {
            int osc = n0 + wn * 8 + tig * 2 + cc;
            int idx = m * NOSC + osc;
            float S  = aS[half * 2 + cc];
            float C  = aC[half * 2 + cc];
            float so = __bfloat162float(sin_r[idx]);
            float co = __bfloat162float(cos_r[idx]);
            float t2 = g_theta[idx] + DT * (omega[osc] + scale * (co * S - so * C));
            float sn, cn;
            __sincosf(t2, &sn, &cn);
            g_theta[idx]      = t2;   // unwrapped; wrap is 2*pi-invariant for trig
            g_sinb[wbuf][idx] = __float2bfloat16(sn);
            g_cosb[wbuf][idx] = __float2bfloat16(cn);
        }
    }
}

// ---------------- finalize: wrap + coherence (accurate fp32) ------------------
__global__ void finalize_kernel(float* __restrict__ out) {
    __shared__ float rs[256], rc[256];
    const int b = blockIdx.x, tid = threadIdx.x;
    float ss = 0.f, cs = 0.f;
    for (int j = tid; j < NOSC; j += 256) {
        int idx = b * NOSC + j;
        float t = g_theta[idx];
        float sn = sinf(t), cn = cosf(t);
        out[idx] = atan2f(sn, cn);        // wrap to (-pi, pi], matches reference
        ss += sn; cs += cn;
    }
    rs[tid] = ss; rc[tid] = cs;
    __syncthreads();
    for (int off = 128; off > 0; off >>= 1) {
        if (tid < off) { rs[tid] += rs[tid + off]; rc[tid] += rc[tid + off]; }
        __syncthreads();
    }
    if (tid == 0) {
        float sm2 = rs[0] * (1.0f / NOSC);
        float cm  = rc[0] * (1.0f / NOSC);
        out[BN + b] = sqrtf(cm * cm + sm2 * sm2);
    }
}

extern "C" void kernel_launch(void* const* d_in, const int* in_sizes, int n_in,
                              void* d_out, int out_size) {
    const float* theta_init = (const float*)d_in[0];
    const float* K          = (const float*)d_in[1];
    const float* omega      = (const float*)d_in[2];
    const float* kglobal    = (const float*)d_in[3];
    float* out = (float*)d_out;

    cudaFuncSetAttribute(step_kernel, cudaFuncAttributeMaxDynamicSharedMemorySize,
                         SMEM_BYTES);

    init_kernel<<<(NOSC * NOSC) / 1024, 256>>>(theta_init, K);
    dim3 grid(NOSC / TN, BATCH / TM);     // (32, 4) = 128 CTAs
    for (int s = 0; s < STEPS; s++)
        step_kernel<<<grid, 256, SMEM_BYTES>>>(omega, kglobal, s & 1);
    finalize_kernel<<<BATCH, 256>>>(out);
}

// round 8
// speedup vs baseline: 2.6245x; 1.3828x over previous
#include <cuda_runtime.h>
#include <cuda_bf16.h>
#include <math.h>
#include <stdint.h>

#define BATCH 128
#define NOSC  1024
#define STEPS 10
#define DT    0.1f
#define BN    (BATCH*NOSC)

#define TM 32
#define TN 32
#define NCHUNK 16             // k-chunks of 64
#define HCH 8                 // chunks per warpgroup half
#define TILE_B 4096           // 32 rows x 128B, XOR-swizzled, no padding
#define CHUNK_B (3*TILE_B)
#define SMEM_BYTES (NCHUNK*CHUNK_B)   // 196608 B

// ---------------- persistent device state (no allocation allowed) -------------
__device__ float          g_theta[BN];
__device__ __nv_bfloat16  g_sinb[2][BN];
__device__ __nv_bfloat16  g_cosb[2][BN];
__device__ __nv_bfloat16  g_Kb[NOSC*NOSC];

// ---------------- helpers -----------------------------------------------------
__device__ __forceinline__ uint32_t s2u(const void* p) {
    return (uint32_t)__cvta_generic_to_shared(p);
}
__device__ __forceinline__ void cp16(uint32_t dst, const void* src) {
    asm volatile("cp.async.cg.shared.global [%0], [%1], 16;"
                 :: "r"(dst), "l"(src) : "memory");
}
__device__ __forceinline__ void ldsm4(uint32_t& r0, uint32_t& r1, uint32_t& r2,
                                      uint32_t& r3, uint32_t a) {
    asm volatile("ldmatrix.sync.aligned.m8n8.x4.shared.b16 {%0,%1,%2,%3}, [%4];"
                 : "=r"(r0), "=r"(r1), "=r"(r2), "=r"(r3) : "r"(a));
}
__device__ __forceinline__ void ldsm2(uint32_t& r0, uint32_t& r1, uint32_t a) {
    asm volatile("ldmatrix.sync.aligned.m8n8.x2.shared.b16 {%0,%1}, [%2];"
                 : "=r"(r0), "=r"(r1) : "r"(a));
}
__device__ __forceinline__ void mma16816(float* d, const uint32_t* a,
                                         uint32_t b0, uint32_t b1) {
    asm volatile(
        "mma.sync.aligned.m16n8k16.row.col.f32.bf16.bf16.f32 "
        "{%0,%1,%2,%3}, {%4,%5,%6,%7}, {%8,%9}, {%0,%1,%2,%3};"
        : "+f"(d[0]), "+f"(d[1]), "+f"(d[2]), "+f"(d[3])
        : "r"(a[0]), "r"(a[1]), "r"(a[2]), "r"(a[3]), "r"(b0), "r"(b1));
}

// ---------------- init (vectorized) -------------------------------------------
__global__ void init_kernel(const float* __restrict__ theta_init,
                            const float* __restrict__ K) {
    int i4 = (blockIdx.x * blockDim.x + threadIdx.x) * 4;
    float4 k4 = *reinterpret_cast<const float4*>(&K[i4]);
    *reinterpret_cast<__nv_bfloat162*>(&g_Kb[i4])     = __floats2bfloat162_rn(k4.x, k4.y);
    *reinterpret_cast<__nv_bfloat162*>(&g_Kb[i4 + 2]) = __floats2bfloat162_rn(k4.z, k4.w);
    if (i4 < BN) {
        float4 t4 = *reinterpret_cast<const float4*>(&theta_init[i4]);
        *reinterpret_cast<float4*>(&g_theta[i4]) = t4;
        float s0 = sinf(t4.x), s1 = sinf(t4.y), s2 = sinf(t4.z), s3 = sinf(t4.w);
        float c0 = cosf(t4.x), c1 = cosf(t4.y), c2 = cosf(t4.z), c3 = cosf(t4.w);
        *reinterpret_cast<__nv_bfloat162*>(&g_sinb[0][i4])     = __floats2bfloat162_rn(s0, s1);
        *reinterpret_cast<__nv_bfloat162*>(&g_sinb[0][i4 + 2]) = __floats2bfloat162_rn(s2, s3);
        *reinterpret_cast<__nv_bfloat162*>(&g_cosb[0][i4])     = __floats2bfloat162_rn(c0, c1);
        *reinterpret_cast<__nv_bfloat162*>(&g_cosb[0][i4 + 2]) = __floats2bfloat162_rn(c2, c3);
    }
}

// ---------------- per-chunk compute -------------------------------------------
__device__ __forceinline__ void compute_chunk(
    uint32_t cb, uint32_t a_row, int ax, int asg,
    uint32_t b_row, int bx, int bsg, float* aS, float* aC)
{
#pragma unroll
    for (int kk = 0; kk < 4; kk++) {
        uint32_t aA = cb + a_row + (uint32_t)((((kk * 2 + asg) ^ ax)) << 4);
        uint32_t aB = cb + 2 * TILE_B + b_row + (uint32_t)((((kk * 2 + bsg) ^ bx)) << 4);
        uint32_t sa[4], ca[4], b0, b1;
        ldsm4(sa[0], sa[1], sa[2], sa[3], aA);
        ldsm4(ca[0], ca[1], ca[2], ca[3], aA + TILE_B);
        ldsm2(b0, b1, aB);
        mma16816(aS, sa, b0, b1);
        mma16816(aC, ca, b0, b1);
    }
}

// ---------------- fused step: 512 thr, intra-CTA split-K ----------------------
__global__ __launch_bounds__(512, 1) void step_kernel(const float* __restrict__ omega,
                                                      const float* __restrict__ kg,
                                                      int rb) {
    extern __shared__ __nv_bfloat16 sm[];
    const uint32_t sb = s2u(sm);

    const int tid  = threadIdx.x;
    const int lane = tid & 31;
    const int wid  = tid >> 5;          // 0..15
    const int hid  = wid >> 3;          // warpgroup half: 0 or 1
    const int htid = tid & 255;
    const int hwid = wid & 7;
    const int n0   = blockIdx.x * TN;
    const int m0   = blockIdx.y * TM;
    const int wy   = hwid & 1;
    const int wn   = hwid >> 1;
    const int wbuf = rb ^ 1;

    const __nv_bfloat16* sin_r = g_sinb[rb];
    const __nv_bfloat16* cos_r = g_cosb[rb];

    // ---- wg0: prefetch epilogue inputs NOW (latency hidden under mainloop) ---
    const int g = lane >> 2, tig = lane & 3;
    const int oscb = n0 + wn * 8 + tig * 2;
    float th[2][2], so[2][2], co[2][2], om[2];
    if (hid == 0) {
        om[0] = omega[oscb]; om[1] = omega[oscb + 1];
#pragma unroll
        for (int half = 0; half < 2; half++) {
            int m = m0 + wy * 16 + half * 8 + g;
#pragma unroll
            for (int cc = 0; cc < 2; cc++) {
                int idx = m * NOSC + oscb + cc;
                th[half][cc] = g_theta[idx];
                so[half][cc] = __bfloat162float(sin_r[idx]);
                co[half][cc] = __bfloat162float(cos_r[idx]);
            }
        }
    }

    // ---- each half loads ITS OWN 8 chunks (8 commit groups per thread) -------
    {
        const int row = htid >> 3;
        const int seg = htid & 7;
        const uint32_t doff = (uint32_t)(row * 128 + ((seg ^ (row & 7)) << 4));
        const int c0 = hid * HCH;
        const __nv_bfloat16* pS = sin_r + (size_t)(m0 + row) * NOSC + seg * 8 + c0 * 64;
        const __nv_bfloat16* pC = cos_r + (size_t)(m0 + row) * NOSC + seg * 8 + c0 * 64;
        const __nv_bfloat16* pB = g_Kb  + (size_t)(n0 + row) * NOSC + seg * 8 + c0 * 64;
        const uint32_t cb0 = sb + c0 * CHUNK_B + doff;
#pragma unroll
        for (int c = 0; c < HCH; c++) {
            cp16(cb0 + c * CHUNK_B,              pS + c * 64);
            cp16(cb0 + c * CHUNK_B + TILE_B,     pC + c * 64);
            cp16(cb0 + c * CHUNK_B + 2 * TILE_B, pB + c * 64);
            asm volatile("cp.async.commit_group;" ::: "memory");
        }
    }

    // ---- fragment addressing (swizzled) --------------------------------------
    const int ar  = wy * 16 + ((lane >> 3) & 1) * 8 + (lane & 7);
    const int asg = lane >> 4;
    const uint32_t a_row = (uint32_t)(ar * 128);
    const int ax  = ar & 7;
    const int l15 = lane & 15;
    const int br  = wn * 8 + (l15 & 7);
    const int bsg = (l15 >> 3) & 1;
    const uint32_t b_row = (uint32_t)(br * 128);
    const int bx  = br & 7;

    float aS[4] = {}, aC[4] = {};
    const uint32_t hbase = sb + hid * HCH * CHUNK_B;
    const int barid = hid + 1;

#define DO_CHUNK(c)                                                              \
    asm volatile("cp.async.wait_group %0;" :: "n"(HCH - 1 - (c)) : "memory");    \
    asm volatile("bar.sync %0, 256;" :: "r"(barid) : "memory");                  \
    compute_chunk(hbase + (c) * CHUNK_B, a_row, ax, asg, b_row, bx, bsg, aS, aC);

    DO_CHUNK(0) DO_CHUNK(1) DO_CHUNK(2) DO_CHUNK(3)
    DO_CHUNK(4) DO_CHUNK(5) DO_CHUNK(6) DO_CHUNK(7)
#undef DO_CHUNK

    // ---- combine halves: wg1 -> smem, wg0 adds + epilogue --------------------
    __syncthreads();
    float* part = (float*)sm;                 // overlays chunk 0 (compute done)
    if (hid == 1) {
#pragma unroll
        for (int i = 0; i < 4; i++) {
            part[i * 256 + htid]       = aS[i];
            part[(4 + i) * 256 + htid] = aC[i];
        }
    }
    __syncthreads();

    if (hid == 0) {
#pragma unroll
        for (int i = 0; i < 4; i++) {
            aS[i] += part[i * 256 + htid];
            aC[i] += part[(4 + i) * 256 + htid];
        }
        const float scale = kg[0] * (1.0f / NOSC);
#pragma unroll
        for (int half = 0; half < 2; half++) {
            int m = m0 + wy * 16 + half * 8 + g;
#pragma unroll
            for (int cc = 0; cc < 2; cc++) {
                int idx = m * NOSC + oscb + cc;
                float S = aS[half * 2 + cc], C = aC[half * 2 + cc];
                float t2 = th[half][cc]
                         + DT * (om[cc] + scale * (co[half][cc] * S - so[half][cc] * C));
                float sn, cn;
                __sincosf(t2, &sn, &cn);
                g_theta[idx]      = t2;   // unwrapped; wrap is 2*pi-invariant
                g_sinb[wbuf][idx] = __float2bfloat16(sn);
                g_cosb[wbuf][idx] = __float2bfloat16(cn);
            }
        }
    }
}

// ---------------- finalize: wrap + coherence (accurate fp32) ------------------
__global__ void finalize_kernel(float* __restrict__ out) {
    __shared__ float rs[256], rc[256];
    const int b = blockIdx.x, tid = threadIdx.x;
    float ss = 0.f, cs = 0.f;
    for (int j = tid; j < NOSC; j += 256) {
        int idx = b * NOSC + j;
        float t = g_theta[idx];
        float sn = sinf(t), cn = cosf(t);
        out[idx] = atan2f(sn, cn);        // wrap to (-pi, pi], matches reference
        ss += sn; cs += cn;
    }
    rs[tid] = ss; rc[tid] = cs;
    __syncthreads();
    for (int off = 128; off > 0; off >>= 1) {
        if (tid < off) { rs[tid] += rs[tid + off]; rc[tid] += rc[tid + off]; }
        __syncthreads();
    }
    if (tid == 0) {
        float sm2 = rs[0] * (1.0f / NOSC);
        float cm  = rc[0] * (1.0f / NOSC);
        out[BN + b] = sqrtf(cm * cm + sm2 * sm2);
    }
}

extern "C" void kernel_launch(void* const* d_in, const int* in_sizes, int n_in,
                              void* d_out, int out_size) {
    const float* theta_init = (const float*)d_in[0];
    const float* K          = (const float*)d_in[1];
    const float* omega      = (const float*)d_in[2];
    const float* kglobal    = (const float*)d_in[3];
    float* out = (float*)d_out;

    cudaFuncSetAttribute(step_kernel, cudaFuncAttributeMaxDynamicSharedMemorySize,
                         SMEM_BYTES);

    init_kernel<<<(NOSC * NOSC) / 1024, 256>>>(theta_init, K);
    dim3 grid(NOSC / TN, BATCH / TM);     // (32, 4) = 128 CTAs
    for (int s = 0; s < STEPS; s++)
        step_kernel<<<grid, 512, SMEM_BYTES>>>(omega, kglobal, s & 1);
    finalize_kernel<<<BATCH, 256>>>(out);
}

// round 9
// speedup vs baseline: 2.6257x; 1.0005x over previous
#include <cuda_runtime.h>
#include <cuda_bf16.h>
#include <math.h>
#include <stdint.h>

#define BATCH 128
#define NOSC  1024
#define STEPS 10
#define DT    0.1f
#define BN    (BATCH*NOSC)

#define TM 32
#define TN 32
#define NCHUNK 16             // k-chunks of 64
#define QCH 4                 // chunks per quarter
#define TILE_B 4096           // 32 rows x 128B, XOR-swizzled, no padding
#define CHUNK_B (3*TILE_B)
#define SMEM_BYTES (NCHUNK*CHUNK_B)   // 196608 B

// ---------------- persistent device state (no allocation allowed) -------------
__device__ float          g_theta[BN];
__device__ __nv_bfloat16  g_sinb[2][BN];
__device__ __nv_bfloat16  g_cosb[2][BN];
__device__ __nv_bfloat16  g_Kb[NOSC*NOSC];

// ---------------- helpers -----------------------------------------------------
__device__ __forceinline__ uint32_t s2u(const void* p) {
    return (uint32_t)__cvta_generic_to_shared(p);
}
__device__ __forceinline__ void cp16(uint32_t dst, const void* src) {
    asm volatile("cp.async.cg.shared.global [%0], [%1], 16;"
                 :: "r"(dst), "l"(src) : "memory");
}
__device__ __forceinline__ void ldsm4(uint32_t& r0, uint32_t& r1, uint32_t& r2,
                                      uint32_t& r3, uint32_t a) {
    asm volatile("ldmatrix.sync.aligned.m8n8.x4.shared.b16 {%0,%1,%2,%3}, [%4];"
                 : "=r"(r0), "=r"(r1), "=r"(r2), "=r"(r3) : "r"(a));
}
__device__ __forceinline__ void ldsm2(uint32_t& r0, uint32_t& r1, uint32_t a) {
    asm volatile("ldmatrix.sync.aligned.m8n8.x2.shared.b16 {%0,%1}, [%2];"
                 : "=r"(r0), "=r"(r1) : "r"(a));
}
__device__ __forceinline__ void mma16816(float* d, const uint32_t* a,
                                         uint32_t b0, uint32_t b1) {
    asm volatile(
        "mma.sync.aligned.m16n8k16.row.col.f32.bf16.bf16.f32 "
        "{%0,%1,%2,%3}, {%4,%5,%6,%7}, {%8,%9}, {%0,%1,%2,%3};"
        : "+f"(d[0]), "+f"(d[1]), "+f"(d[2]), "+f"(d[3])
        : "r"(a[0]), "r"(a[1]), "r"(a[2]), "r"(a[3]), "r"(b0), "r"(b1));
}

// ---------------- init (vectorized) -------------------------------------------
__global__ void init_kernel(const float* __restrict__ theta_init,
                            const float* __restrict__ K) {
    int i4 = (blockIdx.x * blockDim.x + threadIdx.x) * 4;
    float4 k4 = *reinterpret_cast<const float4*>(&K[i4]);
    *reinterpret_cast<__nv_bfloat162*>(&g_Kb[i4])     = __floats2bfloat162_rn(k4.x, k4.y);
    *reinterpret_cast<__nv_bfloat162*>(&g_Kb[i4 + 2]) = __floats2bfloat162_rn(k4.z, k4.w);
    if (i4 < BN) {
        float4 t4 = *reinterpret_cast<const float4*>(&theta_init[i4]);
        *reinterpret_cast<float4*>(&g_theta[i4]) = t4;
        float s0 = sinf(t4.x), s1 = sinf(t4.y), s2 = sinf(t4.z), s3 = sinf(t4.w);
        float c0 = cosf(t4.x), c1 = cosf(t4.y), c2 = cosf(t4.z), c3 = cosf(t4.w);
        *reinterpret_cast<__nv_bfloat162*>(&g_sinb[0][i4])     = __floats2bfloat162_rn(s0, s1);
        *reinterpret_cast<__nv_bfloat162*>(&g_sinb[0][i4 + 2]) = __floats2bfloat162_rn(s2, s3);
        *reinterpret_cast<__nv_bfloat162*>(&g_cosb[0][i4])     = __floats2bfloat162_rn(c0, c1);
        *reinterpret_cast<__nv_bfloat162*>(&g_cosb[0][i4 + 2]) = __floats2bfloat162_rn(c2, c3);
    }
}

// ---------------- per-chunk compute -------------------------------------------
__device__ __forceinline__ void compute_chunk(
    uint32_t cb, uint32_t a_row, int ax, int asg,
    uint32_t b_row, int bx, int bsg, float* aS, float* aC)
{
#pragma unroll
    for (int kk = 0; kk < 4; kk++) {
        uint32_t aA = cb + a_row + (uint32_t)((((kk * 2 + asg) ^ ax)) << 4);
        uint32_t aB = cb + 2 * TILE_B + b_row + (uint32_t)((((kk * 2 + bsg) ^ bx)) << 4);
        uint32_t sa[4], ca[4], b0, b1;
        ldsm4(sa[0], sa[1], sa[2], sa[3], aA);
        ldsm4(ca[0], ca[1], ca[2], ca[3], aA + TILE_B);
        ldsm2(b0, b1, aB);
        mma16816(aS, sa, b0, b1);
        mma16816(aC, ca, b0, b1);
    }
}

// ---------------- fused step: 1024 thr, 4-way intra-CTA split-K ---------------
__global__ __launch_bounds__(1024, 1) void step_kernel(const float* __restrict__ omega,
                                                       const float* __restrict__ kg,
                                                       int rb) {
    extern __shared__ __nv_bfloat16 sm[];
    const uint32_t sb = s2u(sm);

    const int tid  = threadIdx.x;
    const int lane = tid & 31;
    const int wid  = tid >> 5;          // 0..31
    const int qid  = wid >> 3;          // quarter: 0..3
    const int qtid = tid & 255;
    const int qwid = wid & 7;
    const int n0   = blockIdx.x * TN;
    const int m0   = blockIdx.y * TM;
    const int wy   = qwid & 1;
    const int wn   = qwid >> 1;
    const int wbuf = rb ^ 1;

    const __nv_bfloat16* sin_r = g_sinb[rb];
    const __nv_bfloat16* cos_r = g_cosb[rb];

    // ---- quarter 0: prefetch epilogue inputs (hidden under mainloop) ---------
    const int g = lane >> 2, tig = lane & 3;
    const int oscb = n0 + wn * 8 + tig * 2;
    float th[2][2], so[2][2], co[2][2], om[2];
    if (qid == 0) {
        om[0] = omega[oscb]; om[1] = omega[oscb + 1];
#pragma unroll
        for (int half = 0; half < 2; half++) {
            int m = m0 + wy * 16 + half * 8 + g;
#pragma unroll
            for (int cc = 0; cc < 2; cc++) {
                int idx = m * NOSC + oscb + cc;
                th[half][cc] = g_theta[idx];
                so[half][cc] = __bfloat162float(sin_r[idx]);
                co[half][cc] = __bfloat162float(cos_r[idx]);
            }
        }
    }

    // ---- each quarter loads ITS OWN 4 chunks (4 commit groups/thread) --------
    {
        const int row = qtid >> 3;
        const int seg = qtid & 7;
        const uint32_t doff = (uint32_t)(row * 128 + ((seg ^ (row & 7)) << 4));
        const int c0 = qid * QCH;
        const __nv_bfloat16* pS = sin_r + (size_t)(m0 + row) * NOSC + seg * 8 + c0 * 64;
        const __nv_bfloat16* pC = cos_r + (size_t)(m0 + row) * NOSC + seg * 8 + c0 * 64;
        const __nv_bfloat16* pB = g_Kb  + (size_t)(n0 + row) * NOSC + seg * 8 + c0 * 64;
        const uint32_t cb0 = sb + c0 * CHUNK_B + doff;
#pragma unroll
        for (int c = 0; c < QCH; c++) {
            cp16(cb0 + c * CHUNK_B,              pS + c * 64);
            cp16(cb0 + c * CHUNK_B + TILE_B,     pC + c * 64);
            cp16(cb0 + c * CHUNK_B + 2 * TILE_B, pB + c * 64);
            asm volatile("cp.async.commit_group;" ::: "memory");
        }
    }

    // ---- fragment addressing (swizzled) --------------------------------------
    const int ar  = wy * 16 + ((lane >> 3) & 1) * 8 + (lane & 7);
    const int asg = lane >> 4;
    const uint32_t a_row = (uint32_t)(ar * 128);
    const int ax  = ar & 7;
    const int l15 = lane & 15;
    const int br  = wn * 8 + (l15 & 7);
    const int bsg = (l15 >> 3) & 1;
    const uint32_t b_row = (uint32_t)(br * 128);
    const int bx  = br & 7;

    float aS[4] = {}, aC[4] = {};
    const uint32_t qbase = sb + qid * QCH * CHUNK_B;
    const int barid = qid + 1;

#define DO_CHUNK(c)                                                              \
    asm volatile("cp.async.wait_group %0;" :: "n"(QCH - 1 - (c)) : "memory");    \
    asm volatile("bar.sync %0, 256;" :: "r"(barid) : "memory");                  \
    compute_chunk(qbase + (c) * CHUNK_B, a_row, ax, asg, b_row, bx, bsg, aS, aC);

    DO_CHUNK(0) DO_CHUNK(1) DO_CHUNK(2) DO_CHUNK(3)
#undef DO_CHUNK

    // ---- combine quarters: q1..q3 -> smem, q0 adds + epilogue ----------------
    __syncthreads();
    float* part = (float*)sm;                 // overlays chunks 0-1 (compute done)
    if (qid != 0) {
        float* pq = part + (qid - 1) * 8 * 256;
#pragma unroll
        for (int i = 0; i < 4; i++) {
            pq[i * 256 + qtid]       = aS[i];
            pq[(4 + i) * 256 + qtid] = aC[i];
        }
    }
    __syncthreads();

    if (qid == 0) {
#pragma unroll
        for (int q = 0; q < 3; q++) {
            float* pq = part + q * 8 * 256;
#pragma unroll
            for (int i = 0; i < 4; i++) {
                aS[i] += pq[i * 256 + qtid];
                aC[i] += pq[(4 + i) * 256 + qtid];
            }
        }
        const float scale = kg[0] * (1.0f / NOSC);
#pragma unroll
        for (int half = 0; half < 2; half++) {
            int m = m0 + wy * 16 + half * 8 + g;
#pragma unroll
            for (int cc = 0; cc < 2; cc++) {
                int idx = m * NOSC + oscb + cc;
                float S = aS[half * 2 + cc], C = aC[half * 2 + cc];
                float t2 = th[half][cc]
                         + DT * (om[cc] + scale * (co[half][cc] * S - so[half][cc] * C));
                float sn, cn;
                __sincosf(t2, &sn, &cn);
                g_theta[idx]      = t2;   // unwrapped; wrap is 2*pi-invariant
                g_sinb[wbuf][idx] = __float2bfloat16(sn);
                g_cosb[wbuf][idx] = __float2bfloat16(cn);
            }
        }
    }
}

// ---------------- finalize: wrap + coherence (accurate fp32) ------------------
__global__ void finalize_kernel(float* __restrict__ out) {
    __shared__ float rs[256], rc[256];
    const int b = blockIdx.x, tid = threadIdx.x;
    float ss = 0.f, cs = 0.f;
    for (int j = tid; j < NOSC; j += 256) {
        int idx = b * NOSC + j;
        float t = g_theta[idx];
        float sn = sinf(t), cn = cosf(t);
        out[idx] = atan2f(sn, cn);        // wrap to (-pi, pi], matches reference
        ss += sn; cs += cn;
    }
    rs[tid] = ss; rc[tid] = cs;
    __syncthreads();
    for (int off = 128; off > 0; off >>= 1) {
        if (tid < off) { rs[tid] += rs[tid + off]; rc[tid] += rc[tid + off]; }
        __syncthreads();
    }
    if (tid == 0) {
        float sm2 = rs[0] * (1.0f / NOSC);
        float cm  = rc[0] * (1.0f / NOSC);
        out[BN + b] = sqrtf(cm * cm + sm2 * sm2);
    }
}

extern "C" void kernel_launch(void* const* d_in, const int* in_sizes, int n_in,
                              void* d_out, int out_size) {
    const float* theta_init = (const float*)d_in[0];
    const float* K          = (const float*)d_in[1];
    const float* omega      = (const float*)d_in[2];
    const float* kglobal    = (const float*)d_in[3];
    float* out = (float*)d_out;

    cudaFuncSetAttribute(step_kernel, cudaFuncAttributeMaxDynamicSharedMemorySize,
                         SMEM_BYTES);

    init_kernel<<<(NOSC * NOSC) / 1024, 256>>>(theta_init, K);
    dim3 grid(NOSC / TN, BATCH / TM);     // (32, 4) = 128 CTAs
    for (int s = 0; s < STEPS; s++)
        step_kernel<<<grid, 1024, SMEM_BYTES>>>(omega, kglobal, s & 1);
    finalize_kernel<<<BATCH, 256>>>(out);
}

// round 10
// speedup vs baseline: 3.0897x; 1.1767x over previous
#include <cuda_runtime.h>
#include <cuda_bf16.h>
#include <math.h>
#include <stdint.h>

#define BATCH 128
#define NOSC  1024
#define STEPS 10
#define DT    0.1f
#define BN    (BATCH*NOSC)

#define TM 32
#define TN 32
#define NCHUNK 16             // k-chunks of 64
#define QCH 4                 // chunks per quarter
#define TILE_B 4096           // 32 rows x 128B, XOR-swizzled
#define CHUNK_B (3*TILE_B)
#define SMEM_BYTES (NCHUNK*CHUNK_B)   // 196608 B

// ---------------- persistent device state (no allocation allowed) -------------
__device__ float          g_theta[BN];
__device__ __nv_bfloat16  g_sinb[2][BN];
__device__ __nv_bfloat16  g_cosb[2][BN];
__device__ __nv_bfloat16  g_Kb[NOSC*NOSC];

// ---------------- helpers -----------------------------------------------------
__device__ __forceinline__ uint32_t s2u(const void* p) {
    return (uint32_t)__cvta_generic_to_shared(p);
}
__device__ __forceinline__ void cp16(uint32_t dst, const void* src) {
    asm volatile("cp.async.cg.shared.global [%0], [%1], 16;"
                 :: "r"(dst), "l"(src) : "memory");
}
__device__ __forceinline__ void ldsm4(uint32_t& r0, uint32_t& r1, uint32_t& r2,
                                      uint32_t& r3, uint32_t a) {
    asm volatile("ldmatrix.sync.aligned.m8n8.x4.shared.b16 {%0,%1,%2,%3}, [%4];"
                 : "=r"(r0), "=r"(r1), "=r"(r2), "=r"(r3) : "r"(a));
}
__device__ __forceinline__ void mma16816(float* d, const uint32_t* a,
                                         uint32_t b0, uint32_t b1) {
    asm volatile(
        "mma.sync.aligned.m16n8k16.row.col.f32.bf16.bf16.f32 "
        "{%0,%1,%2,%3}, {%4,%5,%6,%7}, {%8,%9}, {%0,%1,%2,%3};"
        : "+f"(d[0]), "+f"(d[1]), "+f"(d[2]), "+f"(d[3])
        : "r"(a[0]), "r"(a[1]), "r"(a[2]), "r"(a[3]), "r"(b0), "r"(b1));
}

// ---------------- init (vectorized) -------------------------------------------
__global__ void init_kernel(const float* __restrict__ theta_init,
                            const float* __restrict__ K) {
    int i4 = (blockIdx.x * blockDim.x + threadIdx.x) * 4;
    float4 k4 = *reinterpret_cast<const float4*>(&K[i4]);
    *reinterpret_cast<__nv_bfloat162*>(&g_Kb[i4])     = __floats2bfloat162_rn(k4.x, k4.y);
    *reinterpret_cast<__nv_bfloat162*>(&g_Kb[i4 + 2]) = __floats2bfloat162_rn(k4.z, k4.w);
    if (i4 < BN) {
        float4 t4 = *reinterpret_cast<const float4*>(&theta_init[i4]);
        *reinterpret_cast<float4*>(&g_theta[i4]) = t4;
        float s0 = sinf(t4.x), s1 = sinf(t4.y), s2 = sinf(t4.z), s3 = sinf(t4.w);
        float c0 = cosf(t4.x), c1 = cosf(t4.y), c2 = cosf(t4.z), c3 = cosf(t4.w);
        *reinterpret_cast<__nv_bfloat162*>(&g_sinb[0][i4])     = __floats2bfloat162_rn(s0, s1);
        *reinterpret_cast<__nv_bfloat162*>(&g_sinb[0][i4 + 2]) = __floats2bfloat162_rn(s2, s3);
        *reinterpret_cast<__nv_bfloat162*>(&g_cosb[0][i4])     = __floats2bfloat162_rn(c0, c1);
        *reinterpret_cast<__nv_bfloat162*>(&g_cosb[0][i4 + 2]) = __floats2bfloat162_rn(c2, c3);
    }
}

// ---------------- fused step: 512 thr, 4-way split-K, m16n16 warps ------------
__global__ __launch_bounds__(512, 1) void step_kernel(const float* __restrict__ omega,
                                                      const float* __restrict__ kg,
                                                      int rb) {
    extern __shared__ __nv_bfloat16 sm[];
    const uint32_t sb = s2u(sm);

    const int tid  = threadIdx.x;
    const int lane = tid & 31;
    const int wid  = tid >> 5;          // 0..15
    const int qid  = wid >> 2;          // quarter: 0..3 (4 warps each)
    const int qtid = tid & 127;
    const int qwid = wid & 3;
    const int n0   = blockIdx.x * TN;
    const int m0   = blockIdx.y * TM;
    const int wy   = qwid & 1;          // m-half (16 rows)
    const int wn   = qwid >> 1;         // n-half (16 cols)
    const int wbuf = rb ^ 1;

    const __nv_bfloat16* sin_r = g_sinb[rb];
    const __nv_bfloat16* cos_r = g_cosb[rb];

    // ---- quarter 0: prefetch epilogue inputs (hidden under mainloop) ---------
    const int g = lane >> 2, tig = lane & 3;
    float th[2][2][2], so[2][2][2], co[2][2][2], om[2][2];
    if (qid == 0) {
#pragma unroll
        for (int ns = 0; ns < 2; ns++)
#pragma unroll
            for (int cc = 0; cc < 2; cc++)
                om[ns][cc] = omega[n0 + wn * 16 + ns * 8 + tig * 2 + cc];
#pragma unroll
        for (int half = 0; half < 2; half++) {
            int m = m0 + wy * 16 + half * 8 + g;
#pragma unroll
            for (int ns = 0; ns < 2; ns++)
#pragma unroll
                for (int cc = 0; cc < 2; cc++) {
                    int idx = m * NOSC + n0 + wn * 16 + ns * 8 + tig * 2 + cc;
                    th[half][ns][cc] = g_theta[idx];
                    so[half][ns][cc] = __bfloat162float(sin_r[idx]);
                    co[half][ns][cc] = __bfloat162float(cos_r[idx]);
                }
        }
    }

    // ---- each quarter (128 thr) loads ITS OWN 4 chunks -----------------------
    {
        const int seg = qtid & 7;
        const int r0w = qtid >> 3;                 // 0..15
        const int c0 = qid * QCH;
#pragma unroll
        for (int c = 0; c < QCH; c++) {
            const uint32_t cb = sb + (c0 + c) * CHUNK_B;
            const int kofs = (c0 + c) * 64 + seg * 8;
#pragma unroll
            for (int v = 0; v < 2; v++) {
                const int row = r0w + v * 16;
                const uint32_t doff = (uint32_t)(row * 128 + ((seg ^ (row & 7)) << 4));
                cp16(cb + doff,              sin_r + (size_t)(m0 + row) * NOSC + kofs);
                cp16(cb + TILE_B + doff,     cos_r + (size_t)(m0 + row) * NOSC + kofs);
                cp16(cb + 2 * TILE_B + doff, g_Kb  + (size_t)(n0 + row) * NOSC + kofs);
            }
            asm volatile("cp.async.commit_group;" ::: "memory");
        }
    }

    // ---- fragment addressing (swizzled) --------------------------------------
    const int ar  = wy * 16 + ((lane >> 3) & 1) * 8 + (lane & 7);
    const int asg = lane >> 4;
    const uint32_t a_row = (uint32_t)(ar * 128);
    const int ax  = ar & 7;
    // B m16n16: lanes 0-7: n0-7/k0 | 8-15: n0-7/k8 | 16-23: n8-15/k0 | 24-31: n8-15/k8
    const int brw = wn * 16 + ((lane >> 4) & 1) * 8 + (lane & 7);
    const int bsg = (lane >> 3) & 1;
    const uint32_t b_row = (uint32_t)(brw * 128);
    const int bx  = brw & 7;

    float aS[2][4] = {}, aC[2][4] = {};
    const uint32_t qbase = sb + qid * QCH * CHUNK_B;
    const int barid = qid + 1;

#define DO_CHUNK(c)                                                              \
    asm volatile("cp.async.wait_group %0;" :: "n"(QCH - 1 - (c)) : "memory");    \
    asm volatile("bar.sync %0, 128;" :: "r"(barid) : "memory");                  \
    {                                                                            \
        const uint32_t cb = qbase + (c) * CHUNK_B;                               \
        _Pragma("unroll")                                                        \
        for (int kk = 0; kk < 4; kk++) {                                         \
            uint32_t aA = cb + a_row + (uint32_t)(((kk * 2 + asg) ^ ax) << 4);   \
            uint32_t aB = cb + 2 * TILE_B + b_row                                \
                        + (uint32_t)(((kk * 2 + bsg) ^ bx) << 4);                \
            uint32_t sa[4], ca[4], bb[4];                                        \
            ldsm4(sa[0], sa[1], sa[2], sa[3], aA);                               \
            ldsm4(ca[0], ca[1], ca[2], ca[3], aA + TILE_B);                      \
            ldsm4(bb[0], bb[1], bb[2], bb[3], aB);                               \
            mma16816(aS[0], sa, bb[0], bb[1]);                                   \
            mma16816(aS[1], sa, bb[2], bb[3]);                                   \
            mma16816(aC[0], ca, bb[0], bb[1]);                                   \
            mma16816(aC[1], ca, bb[2], bb[3]);                                   \
        }                                                                        \
    }

    DO_CHUNK(0) DO_CHUNK(1) DO_CHUNK(2) DO_CHUNK(3)
#undef DO_CHUNK

    // ---- combine quarters: q1..q3 -> smem, q0 adds + epilogue ----------------
    __syncthreads();
    float* part = (float*)sm;                 // overlays chunks 0-1 (24KB, done)
    if (qid != 0) {
        float* pq = part + (qid - 1) * 2048;
#pragma unroll
        for (int ns = 0; ns < 2; ns++)
#pragma unroll
            for (int i = 0; i < 4; i++) {
                pq[(ns * 4 + i) * 128 + qtid]     = aS[ns][i];
                pq[(8 + ns * 4 + i) * 128 + qtid] = aC[ns][i];
            }
    }
    __syncthreads();

    if (qid == 0) {
#pragma unroll
        for (int q = 0; q < 3; q++) {
            float* pq = part + q * 2048;
#pragma unroll
            for (int ns = 0; ns < 2; ns++)
#pragma unroll
                for (int i = 0; i < 4; i++) {
                    aS[ns][i] += pq[(ns * 4 + i) * 128 + qtid];
                    aC[ns][i] += pq[(8 + ns * 4 + i) * 128 + qtid];
                }
        }
        const float scale = kg[0] * (1.0f / NOSC);
#pragma unroll
        for (int half = 0; half < 2; half++) {
            int m = m0 + wy * 16 + half * 8 + g;
#pragma unroll
            for (int ns = 0; ns < 2; ns++)
#pragma unroll
                for (int cc = 0; cc < 2; cc++) {
                    int idx = m * NOSC + n0 + wn * 16 + ns * 8 + tig * 2 + cc;
                    float S = aS[ns][half * 2 + cc], C = aC[ns][half * 2 + cc];
                    float t2 = th[half][ns][cc]
                             + DT * (om[ns][cc]
                             + scale * (co[half][ns][cc] * S - so[half][ns][cc] * C));
                    float sn, cn;
                    __sincosf(t2, &sn, &cn);
                    g_theta[idx]      = t2;   // unwrapped; wrap is 2*pi-invariant
                    g_sinb[wbuf][idx] = __float2bfloat16(sn);
                    g_cosb[wbuf][idx] = __float2bfloat16(cn);
                }
        }
    }
}

// ---------------- finalize: wrap + coherence (accurate fp32) ------------------
__global__ void finalize_kernel(float* __restrict__ out) {
    __shared__ float rs[256], rc[256];
    const int b = blockIdx.x, tid = threadIdx.x;
    float ss = 0.f, cs = 0.f;
    for (int j = tid; j < NOSC; j += 256) {
        int idx = b * NOSC + j;
        float t = g_theta[idx];
        float sn = sinf(t), cn = cosf(t);
        out[idx] = atan2f(sn, cn);        // wrap to (-pi, pi], matches reference
        ss += sn; cs += cn;
    }
    rs[tid] = ss; rc[tid] = cs;
    __syncthreads();
    for (int off = 128; off > 0; off >>= 1) {
        if (tid < off) { rs[tid] += rs[tid + off]; rc[tid] += rc[tid + off]; }
        __syncthreads();
    }
    if (tid == 0) {
        float sm2 = rs[0] * (1.0f / NOSC);
        float cm  = rc[0] * (1.0f / NOSC);
        out[BN + b] = sqrtf(cm * cm + sm2 * sm2);
    }
}

extern "C" void kernel_launch(void* const* d_in, const int* in_sizes, int n_in,
                              void* d_out, int out_size) {
    const float* theta_init = (const float*)d_in[0];
    const float* K          = (const float*)d_in[1];
    const float* omega      = (const float*)d_in[2];
    const float* kglobal    = (const float*)d_in[3];
    float* out = (float*)d_out;

    cudaFuncSetAttribute(step_kernel, cudaFuncAttributeMaxDynamicSharedMemorySize,
                         SMEM_BYTES);

    init_kernel<<<(NOSC * NOSC) / 1024, 256>>>(theta_init, K);
    dim3 grid(NOSC / TN, BATCH / TM);     // (32, 4) = 128 CTAs
    for (int s = 0; s < STEPS; s++)
        step_kernel<<<grid, 512, SMEM_BYTES>>>(omega, kglobal, s & 1);
    finalize_kernel<<<BATCH, 256>>>(out);
}